// round 2
// baseline (speedup 1.0000x reference)
#include <cuda_runtime.h>

#define N_NODES 100000
#define N_EDGES 1600000
#define F 128
#define GRID1 444            // ~3 blocks per SM
#define BN_EPS 1e-5f

// -------- scratch (static device allocations are allowed) --------
__device__ int   g_row_ptr[N_NODES + 1];
__device__ float g_psum[GRID1 * F];    // per-block partial sums for BN
__device__ float g_psq [GRID1 * F];    // per-block partial sums of squares
__device__ float g_scale[F];
__device__ float g_shift[F];

// packed fp32x2 fma (Blackwell; ptxas won't auto-fuse this)
__device__ __forceinline__ unsigned long long ffma2(unsigned long long a,
                                                    unsigned long long b,
                                                    unsigned long long c) {
    unsigned long long d;
    asm("fma.rn.f32x2 %0, %1, %2, %3;" : "=l"(d) : "l"(a), "l"(b), "l"(c));
    return d;
}

// ---------------- kernel 0: row_ptr via searchsorted ----------------
__global__ void k_rowptr(const int* __restrict__ adj_row) {
    int r = blockIdx.x * blockDim.x + threadIdx.x;
    if (r > N_NODES) return;
    int lo = 0, hi = N_EDGES;
    while (lo < hi) {
        int mid = (lo + hi) >> 1;
        if (__ldg(&adj_row[mid]) < r) lo = mid + 1; else hi = mid;
    }
    g_row_ptr[r] = lo;   // lower_bound; r==N_NODES gives N_EDGES
}

// ------------- kernel 1: fused SpMM + Linear (+BN partials) -------------
__global__ void __launch_bounds__(128, 3)
k_main(const float* __restrict__ x,
       const int*   __restrict__ adj_col,
       const float* __restrict__ adj_val,
       const float* __restrict__ fc_w,
       const float* __restrict__ fc_b,
       float*       __restrict__ h_out) {
    __shared__ float agg_sm[F];

    const int t = threadIdx.x;

    // thread t owns output feature t: keep W[t, :] in registers as 64 packed pairs
    unsigned long long w2[F / 2];
    const unsigned long long* wrow =
        reinterpret_cast<const unsigned long long*>(fc_w + (size_t)t * F);
#pragma unroll
    for (int i = 0; i < F / 2; i++) w2[i] = __ldg(&wrow[i]);
    const float bias = __ldg(&fc_b[t]);

    float bn_s = 0.f, bn_q = 0.f;

    for (int n = blockIdx.x; n < N_NODES; n += gridDim.x) {
        const int s = g_row_ptr[n];
        const int e = g_row_ptr[n + 1];

        // ---- SpMM: agg[t] = sum_e val[e] * x[col[e]][t] ----
        float acc = 0.f;
        int k = s;
        int kal = (s + 3) & ~3; if (kal > e) kal = e;
        for (; k < kal; k++)
            acc += __ldg(&adj_val[k]) * __ldg(&x[(size_t)__ldg(&adj_col[k]) * F + t]);
        for (; k + 4 <= e; k += 4) {
            const int4   c4 = *reinterpret_cast<const int4*>(adj_col + k);
            const float4 v4 = *reinterpret_cast<const float4*>(adj_val + k);
            float x0 = __ldg(&x[(size_t)c4.x * F + t]);
            float x1 = __ldg(&x[(size_t)c4.y * F + t]);
            float x2 = __ldg(&x[(size_t)c4.z * F + t]);
            float x3 = __ldg(&x[(size_t)c4.w * F + t]);
            acc += v4.x * x0;
            acc += v4.y * x1;
            acc += v4.z * x2;
            acc += v4.w * x3;
        }
        for (; k < e; k++)
            acc += __ldg(&adj_val[k]) * __ldg(&x[(size_t)__ldg(&adj_col[k]) * F + t]);

        __syncthreads();          // previous iteration's GEMM reads done
        agg_sm[t] = acc;
        __syncthreads();

        // ---- Linear: h[t] = W[t,:] . agg + b[t], packed fp32x2 ----
        unsigned long long p0 = 0ull, p1 = 0ull;  // (0.f,0.f) packed
        const ulonglong2* av = reinterpret_cast<const ulonglong2*>(agg_sm);
#pragma unroll
        for (int j = 0; j < F / 4; j++) {
            ulonglong2 aa = av[j];                 // LDS.128 broadcast
            p0 = ffma2(w2[2 * j],     aa.x, p0);
            p1 = ffma2(w2[2 * j + 1], aa.y, p1);
        }
        float2 f0 = *reinterpret_cast<float2*>(&p0);
        float2 f1 = *reinterpret_cast<float2*>(&p1);
        float hval = (f0.x + f0.y) + (f1.x + f1.y) + bias;

        h_out[(size_t)n * F + t] = hval;
        bn_s += hval;
        bn_q += hval * hval;
    }

    // deterministic BN partials (no atomics)
    g_psum[blockIdx.x * F + t] = bn_s;
    g_psq [blockIdx.x * F + t] = bn_q;
}

// ---------------- kernel 2: finalize BN stats ----------------
__global__ void k_stats(const float* __restrict__ bn_gamma,
                        const float* __restrict__ bn_beta) {
    int o = threadIdx.x;
    if (o >= F) return;
    float s = 0.f, q = 0.f;
#pragma unroll 4
    for (int b = 0; b < GRID1; b++) {
        s += g_psum[b * F + o];
        q += g_psq [b * F + o];
    }
    const float inv_n = 1.0f / (float)N_NODES;
    float mean = s * inv_n;
    float var  = q * inv_n - mean * mean;
    float isd  = rsqrtf(var + BN_EPS);
    float sc   = __ldg(&bn_gamma[o]) * isd;
    g_scale[o] = sc;
    g_shift[o] = __ldg(&bn_beta[o]) - mean * sc;
}

// ---------------- kernel 3: in-place normalize ----------------
__global__ void k_norm(float* __restrict__ h) {
    const size_t total = (size_t)N_NODES * F;
    for (size_t i = ((size_t)blockIdx.x * blockDim.x + threadIdx.x) * 4;
         i < total;
         i += (size_t)gridDim.x * blockDim.x * 4) {
        float4 v = *reinterpret_cast<float4*>(h + i);
        int o = (int)(i & (F - 1));
        v.x = v.x * g_scale[o]     + g_shift[o];
        v.y = v.y * g_scale[o + 1] + g_shift[o + 1];
        v.z = v.z * g_scale[o + 2] + g_shift[o + 2];
        v.w = v.w * g_scale[o + 3] + g_shift[o + 3];
        *reinterpret_cast<float4*>(h + i) = v;
    }
}

// ---------------- launch ----------------
extern "C" void kernel_launch(void* const* d_in, const int* in_sizes, int n_in,
                              void* d_out, int out_size) {
    const float* x        = (const float*)d_in[0];
    const int*   adj_row  = (const int*)  d_in[1];
    const int*   adj_col  = (const int*)  d_in[2];
    const float* adj_val  = (const float*)d_in[3];
    const float* fc_w     = (const float*)d_in[4];
    const float* fc_b     = (const float*)d_in[5];
    const float* bn_gamma = (const float*)d_in[6];
    const float* bn_beta  = (const float*)d_in[7];
    float* out = (float*)d_out;

    k_rowptr<<<(N_NODES + 1 + 255) / 256, 256>>>(adj_row);
    k_main<<<GRID1, 128>>>(x, adj_col, adj_val, fc_w, fc_b, out);
    k_stats<<<1, 128>>>(bn_gamma, bn_beta);
    k_norm<<<(N_NODES * F / 4 + 255) / 256, 256>>>(out);
}

// round 3
// speedup vs baseline: 2.3845x; 2.3845x over previous
#include <cuda_runtime.h>

#define N_NODES 100000
#define N_EDGES 1600000
#define F 128
#define GRID2 296            // GEMM grid: 2 blocks/SM * 148
#define BN_EPS 1e-5f

// -------- scratch (static device allocations are allowed) --------
__device__ int   g_row_ptr[N_NODES + 1];
__device__ float g_agg[(size_t)N_NODES * F];   // SpMM output (51.2 MB)
__device__ float g_psum[GRID2 * F];
__device__ float g_psq [GRID2 * F];
__device__ float g_scale[F];
__device__ float g_shift[F];

// packed fp32x2 fma (Blackwell; ptxas won't auto-fuse this)
__device__ __forceinline__ unsigned long long ffma2(unsigned long long a,
                                                    unsigned long long b,
                                                    unsigned long long c) {
    unsigned long long d;
    asm("fma.rn.f32x2 %0, %1, %2, %3;" : "=l"(d) : "l"(a), "l"(b), "l"(c));
    return d;
}

// ---------------- kernel 0: row_ptr via searchsorted ----------------
__global__ void k_rowptr(const int* __restrict__ adj_row) {
    int r = blockIdx.x * blockDim.x + threadIdx.x;
    if (r > N_NODES) return;
    int lo = 0, hi = N_EDGES;
    while (lo < hi) {
        int mid = (lo + hi) >> 1;
        if (__ldg(&adj_row[mid]) < r) lo = mid + 1; else hi = mid;
    }
    g_row_ptr[r] = lo;   // lower_bound; r==N_NODES gives N_EDGES
}

// ---------------- kernel 1: SpMM, warp-per-node ----------------
// Each warp handles one node; lane owns features [4*lane, 4*lane+4).
// Edges processed 8 at a time -> 8 independent 16B gathers in flight/lane.
__global__ void __launch_bounds__(256)
k_spmm(const float* __restrict__ x,
       const int*   __restrict__ adj_col,
       const float* __restrict__ adj_val) {
    const int n = (blockIdx.x * blockDim.x + threadIdx.x) >> 5;
    if (n >= N_NODES) return;
    const int lane = threadIdx.x & 31;

    const int s = g_row_ptr[n];
    const int e = g_row_ptr[n + 1];
    const float4* xv = reinterpret_cast<const float4*>(x);

    float4 acc = make_float4(0.f, 0.f, 0.f, 0.f);

    int k = s;
    // full chunks of 8 edges
    for (; k + 8 <= e; k += 8) {
        int col = 0; float val = 0.f;
        if (lane < 8) {
            col = __ldg(&adj_col[k + lane]);
            val = __ldg(&adj_val[k + lane]);
        }
#pragma unroll
        for (int j = 0; j < 8; j++) {
            int   c = __shfl_sync(0xffffffffu, col, j);
            float v = __shfl_sync(0xffffffffu, val, j);
            float4 xr = __ldg(&xv[(size_t)c * 32 + lane]);
            acc.x += v * xr.x; acc.y += v * xr.y;
            acc.z += v * xr.z; acc.w += v * xr.w;
        }
    }
    // remainder chunk (predicated)
    if (k < e) {
        int rem = e - k;
        int col = 0; float val = 0.f;
        if (lane < rem) {
            col = __ldg(&adj_col[k + lane]);
            val = __ldg(&adj_val[k + lane]);
        }
#pragma unroll
        for (int j = 0; j < 8; j++) {
            if (j < rem) {
                int   c = __shfl_sync(0xffffffffu, col, j);
                float v = __shfl_sync(0xffffffffu, val, j);
                float4 xr = __ldg(&xv[(size_t)c * 32 + lane]);
                acc.x += v * xr.x; acc.y += v * xr.y;
                acc.z += v * xr.z; acc.w += v * xr.w;
            }
        }
    }

    reinterpret_cast<float4*>(g_agg)[(size_t)n * 32 + lane] = acc;
}

// ------------- kernel 2: Linear (W row per thread) + BN partials -------------
// thread t owns output feature t; 4 nodes per syncthreads pair.
__global__ void __launch_bounds__(128, 2)
k_gemm(const float* __restrict__ fc_w,
       const float* __restrict__ fc_b,
       float*       __restrict__ h_out) {
    __shared__ float agg_sm[4][F];

    const int t = threadIdx.x;

    unsigned long long w2[F / 2];
    const unsigned long long* wrow =
        reinterpret_cast<const unsigned long long*>(fc_w + (size_t)t * F);
#pragma unroll
    for (int i = 0; i < F / 2; i++) w2[i] = __ldg(&wrow[i]);
    const float bias = __ldg(&fc_b[t]);

    float bn_s = 0.f, bn_q = 0.f;

    for (int n0 = blockIdx.x * 4; n0 < N_NODES; n0 += gridDim.x * 4) {
        const int nv = min(4, N_NODES - n0);

        __syncthreads();
#pragma unroll
        for (int r = 0; r < 4; r++)
            if (r < nv) agg_sm[r][t] = g_agg[(size_t)(n0 + r) * F + t];
        __syncthreads();

        unsigned long long p0[4] = {0ull, 0ull, 0ull, 0ull};
        unsigned long long p1[4] = {0ull, 0ull, 0ull, 0ull};
#pragma unroll
        for (int j = 0; j < F / 4; j++) {
#pragma unroll
            for (int r = 0; r < 4; r++) {
                ulonglong2 aa =
                    reinterpret_cast<const ulonglong2*>(agg_sm[r])[j];
                p0[r] = ffma2(w2[2 * j],     aa.x, p0[r]);
                p1[r] = ffma2(w2[2 * j + 1], aa.y, p1[r]);
            }
        }
#pragma unroll
        for (int r = 0; r < 4; r++) {
            if (r < nv) {
                float2 f0 = *reinterpret_cast<float2*>(&p0[r]);
                float2 f1 = *reinterpret_cast<float2*>(&p1[r]);
                float hval = (f0.x + f0.y) + (f1.x + f1.y) + bias;
                h_out[(size_t)(n0 + r) * F + t] = hval;
                bn_s += hval;
                bn_q += hval * hval;
            }
        }
    }

    g_psum[blockIdx.x * F + t] = bn_s;
    g_psq [blockIdx.x * F + t] = bn_q;
}

// ---------------- kernel 3: finalize BN stats ----------------
__global__ void k_stats(const float* __restrict__ bn_gamma,
                        const float* __restrict__ bn_beta) {
    int o = threadIdx.x;
    if (o >= F) return;
    float s = 0.f, q = 0.f;
#pragma unroll 4
    for (int b = 0; b < GRID2; b++) {
        s += g_psum[b * F + o];
        q += g_psq [b * F + o];
    }
    const float inv_n = 1.0f / (float)N_NODES;
    float mean = s * inv_n;
    float var  = q * inv_n - mean * mean;
    float isd  = rsqrtf(var + BN_EPS);
    float sc   = __ldg(&bn_gamma[o]) * isd;
    g_scale[o] = sc;
    g_shift[o] = __ldg(&bn_beta[o]) - mean * sc;
}

// ---------------- kernel 4: in-place normalize ----------------
__global__ void k_norm(float* __restrict__ h) {
    const size_t total = (size_t)N_NODES * F;
    size_t i = ((size_t)blockIdx.x * blockDim.x + threadIdx.x) * 4;
    if (i >= total) return;
    int o = (int)(i & (F - 1));
    float4 v  = *reinterpret_cast<float4*>(h + i);
    float4 sc = *reinterpret_cast<const float4*>(g_scale + o);
    float4 sh = *reinterpret_cast<const float4*>(g_shift + o);
    v.x = v.x * sc.x + sh.x;
    v.y = v.y * sc.y + sh.y;
    v.z = v.z * sc.z + sh.z;
    v.w = v.w * sc.w + sh.w;
    *reinterpret_cast<float4*>(h + i) = v;
}

// ---------------- launch ----------------
extern "C" void kernel_launch(void* const* d_in, const int* in_sizes, int n_in,
                              void* d_out, int out_size) {
    const float* x        = (const float*)d_in[0];
    const int*   adj_row  = (const int*)  d_in[1];
    const int*   adj_col  = (const int*)  d_in[2];
    const float* adj_val  = (const float*)d_in[3];
    const float* fc_w     = (const float*)d_in[4];
    const float* fc_b     = (const float*)d_in[5];
    const float* bn_gamma = (const float*)d_in[6];
    const float* bn_beta  = (const float*)d_in[7];
    float* out = (float*)d_out;

    k_rowptr<<<(N_NODES + 1 + 255) / 256, 256>>>(adj_row);
    k_spmm<<<(N_NODES * 32 + 255) / 256, 256>>>(x, adj_col, adj_val);
    k_gemm<<<GRID2, 128>>>(fc_w, fc_b, out);
    k_stats<<<1, 128>>>(bn_gamma, bn_beta);
    k_norm<<<(N_NODES * F / 4 + 255) / 256, 256>>>(out);
}

// round 4
// speedup vs baseline: 2.6948x; 1.1301x over previous
#include <cuda_runtime.h>

#define N_NODES 100000
#define N_EDGES 1600000
#define F 128
#define GRID2 296            // GEMM grid: 2 blocks/SM * 148
#define BN_EPS 1e-5f

// -------- scratch (static device allocations are allowed) --------
__device__ int   g_row_ptr[N_NODES + 1];
__device__ float g_agg[(size_t)N_NODES * F];   // SpMM output (51.2 MB)
__device__ float g_psum[F * GRID2];            // transposed: [feature][block]
__device__ float g_psq [F * GRID2];
__device__ float g_scale[F];
__device__ float g_shift[F];

// packed fp32x2 fma (Blackwell; ptxas won't auto-fuse this)
__device__ __forceinline__ unsigned long long ffma2(unsigned long long a,
                                                    unsigned long long b,
                                                    unsigned long long c) {
    unsigned long long d;
    asm("fma.rn.f32x2 %0, %1, %2, %3;" : "=l"(d) : "l"(a), "l"(b), "l"(c));
    return d;
}

// ---------------- kernel 0: row_ptr via boundary scatter ----------------
// row_ptr[r] = first edge index with adj_row[idx] >= r (lower_bound).
__global__ void k_rowptr(const int* __restrict__ adj_row) {
    int e = blockIdx.x * blockDim.x + threadIdx.x;
    if (e >= N_EDGES) return;
    int r1 = __ldg(&adj_row[e]);
    if (e == 0) {
        for (int r = 0; r <= r1; r++) g_row_ptr[r] = 0;
    }
    int r2 = (e + 1 < N_EDGES) ? __ldg(&adj_row[e + 1]) : N_NODES;
    for (int r = r1 + 1; r <= r2; r++) g_row_ptr[r] = e + 1;
}

// ---------------- kernel 1: SpMM, warp-per-node ----------------
// Each warp handles one node; lane owns features [4*lane, 4*lane+4).
// Edges processed 16 at a time -> 16 independent 16B gathers in flight/lane.
__global__ void __launch_bounds__(256)
k_spmm(const float* __restrict__ x,
       const int*   __restrict__ adj_col,
       const float* __restrict__ adj_val) {
    const int n = (blockIdx.x * blockDim.x + threadIdx.x) >> 5;
    if (n >= N_NODES) return;
    const int lane = threadIdx.x & 31;

    const int s = g_row_ptr[n];
    const int e = g_row_ptr[n + 1];
    const float4* xv = reinterpret_cast<const float4*>(x);

    float4 acc = make_float4(0.f, 0.f, 0.f, 0.f);

    int k = s;
    for (; k + 16 <= e; k += 16) {
        int col = 0; float val = 0.f;
        if (lane < 16) {
            col = __ldg(&adj_col[k + lane]);
            val = __ldg(&adj_val[k + lane]);
        }
#pragma unroll
        for (int j = 0; j < 16; j++) {
            int   c = __shfl_sync(0xffffffffu, col, j);
            float v = __shfl_sync(0xffffffffu, val, j);
            float4 xr = __ldg(&xv[(size_t)c * 32 + lane]);
            acc.x += v * xr.x; acc.y += v * xr.y;
            acc.z += v * xr.z; acc.w += v * xr.w;
        }
    }
    if (k < e) {
        int rem = e - k;                       // 1..15
        int col = 0; float val = 0.f;
        if (lane < rem) {
            col = __ldg(&adj_col[k + lane]);
            val = __ldg(&adj_val[k + lane]);
        }
#pragma unroll
        for (int j = 0; j < 15; j++) {
            if (j < rem) {
                int   c = __shfl_sync(0xffffffffu, col, j);
                float v = __shfl_sync(0xffffffffu, val, j);
                float4 xr = __ldg(&xv[(size_t)c * 32 + lane]);
                acc.x += v * xr.x; acc.y += v * xr.y;
                acc.z += v * xr.z; acc.w += v * xr.w;
            }
        }
    }

    reinterpret_cast<float4*>(g_agg)[(size_t)n * 32 + lane] = acc;
}

// ------------- kernel 2: Linear (W row per thread) + BN partials -------------
// thread t owns output feature t; 8 nodes per syncthreads pair.
__global__ void __launch_bounds__(128, 2)
k_gemm(const float* __restrict__ fc_w,
       const float* __restrict__ fc_b,
       float*       __restrict__ h_out) {
    __shared__ float agg_sm[8][F];

    const int t = threadIdx.x;

    unsigned long long w2[F / 2];
    const unsigned long long* wrow =
        reinterpret_cast<const unsigned long long*>(fc_w + (size_t)t * F);
#pragma unroll
    for (int i = 0; i < F / 2; i++) w2[i] = __ldg(&wrow[i]);
    const float bias = __ldg(&fc_b[t]);

    float bn_s = 0.f, bn_q = 0.f;

    for (int n0 = blockIdx.x * 8; n0 < N_NODES; n0 += gridDim.x * 8) {
        const int nv = min(8, N_NODES - n0);

        __syncthreads();
#pragma unroll
        for (int r = 0; r < 8; r++)
            if (r < nv) agg_sm[r][t] = g_agg[(size_t)(n0 + r) * F + t];
        __syncthreads();

        unsigned long long p0[8], p1[8];
#pragma unroll
        for (int r = 0; r < 8; r++) { p0[r] = 0ull; p1[r] = 0ull; }

#pragma unroll
        for (int j = 0; j < F / 4; j++) {
#pragma unroll
            for (int r = 0; r < 8; r++) {
                ulonglong2 aa =
                    reinterpret_cast<const ulonglong2*>(agg_sm[r])[j];
                p0[r] = ffma2(w2[2 * j],     aa.x, p0[r]);
                p1[r] = ffma2(w2[2 * j + 1], aa.y, p1[r]);
            }
        }
#pragma unroll
        for (int r = 0; r < 8; r++) {
            if (r < nv) {
                float2 f0 = *reinterpret_cast<float2*>(&p0[r]);
                float2 f1 = *reinterpret_cast<float2*>(&p1[r]);
                float hval = (f0.x + f0.y) + (f1.x + f1.y) + bias;
                h_out[(size_t)(n0 + r) * F + t] = hval;
                bn_s += hval;
                bn_q += hval * hval;
            }
        }
    }

    g_psum[t * GRID2 + blockIdx.x] = bn_s;     // transposed for coalesced stats
    g_psq [t * GRID2 + blockIdx.x] = bn_q;
}

// ---------------- kernel 3: finalize BN stats (parallel) ----------------
// one block per feature; 128 threads reduce GRID2 partials.
__global__ void k_stats(const float* __restrict__ bn_gamma,
                        const float* __restrict__ bn_beta) {
    __shared__ float ss[4], qq[4];
    const int o = blockIdx.x;
    const int t = threadIdx.x;

    float s = 0.f, q = 0.f;
    for (int b = t; b < GRID2; b += 128) {
        s += g_psum[o * GRID2 + b];
        q += g_psq [o * GRID2 + b];
    }
#pragma unroll
    for (int off = 16; off; off >>= 1) {
        s += __shfl_down_sync(0xffffffffu, s, off);
        q += __shfl_down_sync(0xffffffffu, q, off);
    }
    if ((t & 31) == 0) { ss[t >> 5] = s; qq[t >> 5] = q; }
    __syncthreads();
    if (t == 0) {
        s = ss[0] + ss[1] + ss[2] + ss[3];
        q = qq[0] + qq[1] + qq[2] + qq[3];
        const float inv_n = 1.0f / (float)N_NODES;
        float mean = s * inv_n;
        float var  = q * inv_n - mean * mean;
        float isd  = rsqrtf(var + BN_EPS);
        float sc   = __ldg(&bn_gamma[o]) * isd;
        g_scale[o] = sc;
        g_shift[o] = __ldg(&bn_beta[o]) - mean * sc;
    }
}

// ---------------- kernel 4: in-place normalize ----------------
__global__ void k_norm(float* __restrict__ h) {
    const size_t total = (size_t)N_NODES * F;
    size_t i = ((size_t)blockIdx.x * blockDim.x + threadIdx.x) * 4;
    if (i >= total) return;
    int o = (int)(i & (F - 1));
    float4 v  = *reinterpret_cast<float4*>(h + i);
    float4 sc = *reinterpret_cast<const float4*>(g_scale + o);
    float4 sh = *reinterpret_cast<const float4*>(g_shift + o);
    v.x = v.x * sc.x + sh.x;
    v.y = v.y * sc.y + sh.y;
    v.z = v.z * sc.z + sh.z;
    v.w = v.w * sc.w + sh.w;
    *reinterpret_cast<float4*>(h + i) = v;
}

// ---------------- launch ----------------
extern "C" void kernel_launch(void* const* d_in, const int* in_sizes, int n_in,
                              void* d_out, int out_size) {
    const float* x        = (const float*)d_in[0];
    const int*   adj_row  = (const int*)  d_in[1];
    const int*   adj_col  = (const int*)  d_in[2];
    const float* adj_val  = (const float*)d_in[3];
    const float* fc_w     = (const float*)d_in[4];
    const float* fc_b     = (const float*)d_in[5];
    const float* bn_gamma = (const float*)d_in[6];
    const float* bn_beta  = (const float*)d_in[7];
    float* out = (float*)d_out;

    k_rowptr<<<(N_EDGES + 255) / 256, 256>>>(adj_row);
    k_spmm<<<(N_NODES * 32 + 255) / 256, 256>>>(x, adj_col, adj_val);
    k_gemm<<<GRID2, 128>>>(fc_w, fc_b, out);
    k_stats<<<F, 128>>>(bn_gamma, bn_beta);
    k_norm<<<(N_NODES * F / 4 + 255) / 256, 256>>>(out);
}